// round 1
// baseline (speedup 1.0000x reference)
#include <cuda_runtime.h>
#include <math.h>

#define NV 10000
#define EV 160000
#define CV 512
#define HV 4
#define RV 8
#define LLV 2
#define EDV 768
#define OV 128

// ---------------- scratch (device globals; no cudaMalloc allowed) ----------------
__device__ float g_xw[(size_t)NV * RV * CV];     // 164 MB  [n][r][c]
__device__ float g_xA[NV * CV];
__device__ float g_xB[NV * CV];
__device__ float g_h0[NV * CV];
__device__ float g_h1[NV * 2 * CV];              // 41 MB
__device__ float g_Q[NV * RV * HV];
__device__ float g_K[NV * RV * HV];
__device__ float g_P[EDV * LLV * HV];            // [j][l*4+h]
__device__ float g_ae[(size_t)EV * LLV * HV];    // [e][l*4+h]
__device__ float g_alpha[EV * HV];
__device__ unsigned g_maxu[NV * HV];
__device__ float g_den[NV * HV];
__device__ int g_src[EV], g_dst[EV], g_typ[EV];
__device__ int g_cnt[NV], g_off[NV + 1], g_cur[NV];
__device__ int g_perm[EV];
__device__ int g_flags[2];

// ---------------- helpers ----------------
__device__ __forceinline__ float warp_red(float v) {
#pragma unroll
    for (int s = 16; s; s >>= 1) v += __shfl_down_sync(0xffffffffu, v, s);
    return v;
}
__device__ __forceinline__ unsigned fenc(float f) {
    unsigned b = __float_as_uint(f);
    return (b & 0x80000000u) ? ~b : (b | 0x80000000u);
}
__device__ __forceinline__ float fdec(unsigned u) {
    return __uint_as_float((u & 0x80000000u) ? (u ^ 0x80000000u) : ~u);
}

// ---------------- edge index dtype detection + conversion ----------------
__global__ void detect_kernel(const int* __restrict__ a, const int* __restrict__ b) {
    __shared__ int nz[2];
    if (threadIdx.x < 2) nz[threadIdx.x] = 0;
    __syncthreads();
    int i = threadIdx.x;  // 256 threads, inspect odd 32-bit words
    if (a[2 * i + 1] != 0) atomicAdd(&nz[0], 1);
    if (b[2 * i + 1] != 0) atomicAdd(&nz[1], 1);
    __syncthreads();
    if (threadIdx.x == 0) { g_flags[0] = (nz[0] == 0); g_flags[1] = (nz[1] == 0); }
}

__global__ void convert_kernel(const void* __restrict__ ei, const void* __restrict__ et) {
    int e = blockIdx.x * blockDim.x + threadIdx.x;
    if (e >= EV) return;
    int f0 = g_flags[0], f1 = g_flags[1];
    int s, d, t;
    if (f0) {
        const long long* a = (const long long*)ei;
        s = (int)a[e]; d = (int)a[EV + e];
    } else {
        const int* a = (const int*)ei;
        s = a[e]; d = a[EV + e];
    }
    if (f1) t = (int)((const long long*)et)[e];
    else    t = ((const int*)et)[e];
    g_src[e] = s; g_dst[e] = d; g_typ[e] = t;
}

// ---------------- CSR build ----------------
__global__ void reset_cnt_kernel() {
    int i = blockIdx.x * blockDim.x + threadIdx.x;
    if (i < NV) g_cnt[i] = 0;
}
__global__ void hist_kernel() {
    int e = blockIdx.x * blockDim.x + threadIdx.x;
    if (e < EV) atomicAdd(&g_cnt[g_dst[e]], 1);
}
__global__ void scan_kernel() {
    __shared__ int sh[1024];
    __shared__ int carry;
    int t = threadIdx.x;
    if (t == 0) carry = 0;
    __syncthreads();
    for (int base = 0; base < NV; base += 1024) {
        int i = base + t;
        int v = (i < NV) ? g_cnt[i] : 0;
        sh[t] = v;
        __syncthreads();
        for (int s = 1; s < 1024; s <<= 1) {
            int add = (t >= s) ? sh[t - s] : 0;
            __syncthreads();
            sh[t] += add;
            __syncthreads();
        }
        int excl = sh[t] - v + carry;
        if (i < NV) { g_off[i] = excl; g_cur[i] = excl; }
        int tot = sh[1023];
        __syncthreads();
        if (t == 0) carry += tot;
        __syncthreads();
    }
    if (threadIdx.x == 0) g_off[NV] = carry;
}
__global__ void scatter_kernel() {
    int e = blockIdx.x * blockDim.x + threadIdx.x;
    if (e >= EV) return;
    int d = g_dst[e];
    int p = atomicAdd(&g_cur[d], 1);
    g_perm[p] = e;
}

// ---------------- SGEMM 128x128x8, double-buffered, 8x8/thread ----------------
// C[m, n (+ z*cz)] = A[m,:] @ B(z)[:, n]; EPI: 0 none, 1 bias+relu, 2 bias+residual
template <int EPI>
__global__ __launch_bounds__(256)
void sgemm_k(const float* __restrict__ A, const float* __restrict__ B,
             float* __restrict__ C, int M, int Nc, int K,
             int lda, int ldb, int ldc, long bz, long cz,
             const float* __restrict__ bias, const float* __restrict__ res) {
    B += (long)blockIdx.z * bz;
    C += (long)blockIdx.z * cz;
    __shared__ __align__(16) float As[2][8][128];
    __shared__ __align__(16) float Bs[2][8][128];

    int tid = threadIdx.x;
    int tx = tid & 15, ty = tid >> 4;
    int m0 = blockIdx.y * 128;
    int n0 = blockIdx.x * 128;

    int arow = tid >> 1;
    int acol = (tid & 1) * 4;
    int brow = tid >> 5;
    int bcol = (tid & 31) * 4;

    float acc[8][8];
#pragma unroll
    for (int i = 0; i < 8; i++)
#pragma unroll
        for (int j = 0; j < 8; j++) acc[i][j] = 0.f;

    const float* Aptr = A + (long)(m0 + arow) * lda + acol;
    bool arow_ok = (m0 + arow) < M;
    const float* Bptr = B + (long)brow * ldb + n0 + bcol;

    int KT = K >> 3;
    {
        float4 a4 = make_float4(0.f, 0.f, 0.f, 0.f);
        if (arow_ok) a4 = *(const float4*)(Aptr);
        float4 b4 = *(const float4*)(Bptr);
        As[0][acol + 0][arow] = a4.x;
        As[0][acol + 1][arow] = a4.y;
        As[0][acol + 2][arow] = a4.z;
        As[0][acol + 3][arow] = a4.w;
        *(float4*)&Bs[0][brow][bcol] = b4;
    }
    __syncthreads();

    for (int kt = 0; kt < KT; kt++) {
        int buf = kt & 1;
        float4 na4 = make_float4(0.f, 0.f, 0.f, 0.f);
        float4 nb4 = make_float4(0.f, 0.f, 0.f, 0.f);
        bool pf = (kt + 1 < KT);
        if (pf) {
            if (arow_ok) na4 = *(const float4*)(Aptr + (kt + 1) * 8);
            nb4 = *(const float4*)(Bptr + (long)(kt + 1) * 8 * ldb);
        }
#pragma unroll
        for (int kk = 0; kk < 8; kk++) {
            float af[8], bf[8];
            *(float4*)&af[0] = *(const float4*)&As[buf][kk][ty * 4];
            *(float4*)&af[4] = *(const float4*)&As[buf][kk][64 + ty * 4];
            *(float4*)&bf[0] = *(const float4*)&Bs[buf][kk][tx * 4];
            *(float4*)&bf[4] = *(const float4*)&Bs[buf][kk][64 + tx * 4];
#pragma unroll
            for (int i = 0; i < 8; i++)
#pragma unroll
                for (int j = 0; j < 8; j++)
                    acc[i][j] = fmaf(af[i], bf[j], acc[i][j]);
        }
        if (pf) {
            int nb = buf ^ 1;
            As[nb][acol + 0][arow] = na4.x;
            As[nb][acol + 1][arow] = na4.y;
            As[nb][acol + 2][arow] = na4.z;
            As[nb][acol + 3][arow] = na4.w;
            *(float4*)&Bs[nb][brow][bcol] = nb4;
        }
        __syncthreads();
    }

#pragma unroll
    for (int i = 0; i < 8; i++) {
        int m = m0 + ((i < 4) ? (ty * 4 + i) : (64 + ty * 4 + i - 4));
        if (m >= M) continue;
#pragma unroll
        for (int j = 0; j < 8; j++) {
            int n = n0 + ((j < 4) ? (tx * 4 + j) : (64 + tx * 4 + j - 4));
            float v = acc[i][j];
            if (EPI == 1) v = fmaxf(v + bias[n], 0.f);
            if (EPI == 2) v = v + bias[n] + res[(long)m * Nc + n];
            C[(long)m * ldc + n] = v;
        }
    }
}

// ---------------- Q/K projection from xw: one warp per (n,r) row ----------------
__global__ void qk_kernel(const float* __restrict__ qm, const float* __restrict__ km) {
    int rr = blockIdx.x * 8 + (threadIdx.x >> 5);  // rr < NV*RV
    int lane = threadIdx.x & 31;
    const float* row = g_xw + (long)rr * CV;
    float qa0 = 0, qa1 = 0, qa2 = 0, qa3 = 0;
    float ka0 = 0, ka1 = 0, ka2 = 0, ka3 = 0;
#pragma unroll
    for (int j = 0; j < 16; j++) {
        int c = lane + 32 * j;
        float v = row[c];
        float4 q4 = *(const float4*)(qm + c * HV);
        float4 k4 = *(const float4*)(km + c * HV);
        qa0 = fmaf(v, q4.x, qa0); qa1 = fmaf(v, q4.y, qa1);
        qa2 = fmaf(v, q4.z, qa2); qa3 = fmaf(v, q4.w, qa3);
        ka0 = fmaf(v, k4.x, ka0); ka1 = fmaf(v, k4.y, ka1);
        ka2 = fmaf(v, k4.z, ka2); ka3 = fmaf(v, k4.w, ka3);
    }
    qa0 = warp_red(qa0); qa1 = warp_red(qa1); qa2 = warp_red(qa2); qa3 = warp_red(qa3);
    ka0 = warp_red(ka0); ka1 = warp_red(ka1); ka2 = warp_red(ka2); ka3 = warp_red(ka3);
    if (lane == 0) {
        *(float4*)(g_Q + (long)rr * HV) = make_float4(qa0, qa1, qa2, qa3);
        *(float4*)(g_K + (long)rr * HV) = make_float4(ka0, ka1, ka2, ka3);
    }
}

// ---------------- P = We @ e, both layers: one warp per row j ----------------
__global__ void p_kernel(const float* __restrict__ we, const float* __restrict__ ev) {
    int j = blockIdx.x * 8 + (threadIdx.x >> 5);  // j < 768
    int lane = threadIdx.x & 31;
    float a[8];
#pragma unroll
    for (int u = 0; u < 8; u++) a[u] = 0.f;
#pragma unroll
    for (int jj = 0; jj < 16; jj++) {
        int c = lane + 32 * jj;
        float w0 = we[(long)j * CV + c];
        float w1 = we[(long)EDV * CV + (long)j * CV + c];
        float4 e0 = *(const float4*)(ev + c * HV);
        float4 e1 = *(const float4*)(ev + CV * HV + c * HV);
        a[0] = fmaf(w0, e0.x, a[0]); a[1] = fmaf(w0, e0.y, a[1]);
        a[2] = fmaf(w0, e0.z, a[2]); a[3] = fmaf(w0, e0.w, a[3]);
        a[4] = fmaf(w1, e1.x, a[4]); a[5] = fmaf(w1, e1.y, a[5]);
        a[6] = fmaf(w1, e1.z, a[6]); a[7] = fmaf(w1, e1.w, a[7]);
    }
#pragma unroll
    for (int u = 0; u < 8; u++) a[u] = warp_red(a[u]);
    if (lane == 0) {
        *(float4*)(g_P + j * 8) = make_float4(a[0], a[1], a[2], a[3]);
        *(float4*)(g_P + j * 8 + 4) = make_float4(a[4], a[5], a[6], a[7]);
    }
}

// ---------------- ae = eattr @ P, both layers: one warp per edge ----------------
__global__ void ae_kernel(const float* __restrict__ eattr) {
    int e = blockIdx.x * 8 + (threadIdx.x >> 5);  // e < EV
    int lane = threadIdx.x & 31;
    float a[8];
#pragma unroll
    for (int u = 0; u < 8; u++) a[u] = 0.f;
#pragma unroll
    for (int jj = 0; jj < 24; jj++) {
        int j = lane + 32 * jj;
        float v = eattr[(long)e * EDV + j];
        float4 p0 = *(const float4*)(g_P + j * 8);
        float4 p1 = *(const float4*)(g_P + j * 8 + 4);
        a[0] = fmaf(v, p0.x, a[0]); a[1] = fmaf(v, p0.y, a[1]);
        a[2] = fmaf(v, p0.z, a[2]); a[3] = fmaf(v, p0.w, a[3]);
        a[4] = fmaf(v, p1.x, a[4]); a[5] = fmaf(v, p1.y, a[5]);
        a[6] = fmaf(v, p1.z, a[6]); a[7] = fmaf(v, p1.w, a[7]);
    }
#pragma unroll
    for (int u = 0; u < 8; u++) a[u] = warp_red(a[u]);
    if (lane == 0) {
        *(float4*)(g_ae + (long)e * 8) = make_float4(a[0], a[1], a[2], a[3]);
        *(float4*)(g_ae + (long)e * 8 + 4) = make_float4(a[4], a[5], a[6], a[7]);
    }
}

// ---------------- per-layer reset of softmax state ----------------
__global__ void reset_nodes_kernel() {
    int i = blockIdx.x * blockDim.x + threadIdx.x;
    if (i < NV * HV) { g_maxu[i] = 0u; g_den[i] = 0.f; }
}

// ---------------- attention logits + leaky_relu + segment max ----------------
__global__ void logits_kernel(int l) {
    int e = blockIdx.x * blockDim.x + threadIdx.x;
    if (e >= EV) return;
    int dst = g_dst[e], src = g_src[e], t = g_typ[e];
    float4 ae = *(const float4*)(g_ae + (long)e * (LLV * HV) + l * HV);
    float4 qv = *(const float4*)(g_Q + (long)(dst * RV + t) * HV);
    float4 kv = *(const float4*)(g_K + (long)(src * RV + t) * HV);
    float4 a;
    a.x = qv.x + kv.x + ae.x; a.x = a.x > 0.f ? a.x : 0.2f * a.x;
    a.y = qv.y + kv.y + ae.y; a.y = a.y > 0.f ? a.y : 0.2f * a.y;
    a.z = qv.z + kv.z + ae.z; a.z = a.z > 0.f ? a.z : 0.2f * a.z;
    a.w = qv.w + kv.w + ae.w; a.w = a.w > 0.f ? a.w : 0.2f * a.w;
    *(float4*)(g_alpha + (long)e * HV) = a;
    atomicMax(&g_maxu[dst * HV + 0], fenc(a.x));
    atomicMax(&g_maxu[dst * HV + 1], fenc(a.y));
    atomicMax(&g_maxu[dst * HV + 2], fenc(a.z));
    atomicMax(&g_maxu[dst * HV + 3], fenc(a.w));
}

// ---------------- exp + segment sum ----------------
__global__ void expsum_kernel() {
    int e = blockIdx.x * blockDim.x + threadIdx.x;
    if (e >= EV) return;
    int dst = g_dst[e];
    float4 a = *(const float4*)(g_alpha + (long)e * HV);
    a.x = expf(a.x - fdec(g_maxu[dst * HV + 0]));
    a.y = expf(a.y - fdec(g_maxu[dst * HV + 1]));
    a.z = expf(a.z - fdec(g_maxu[dst * HV + 2]));
    a.w = expf(a.w - fdec(g_maxu[dst * HV + 3]));
    *(float4*)(g_alpha + (long)e * HV) = a;
    atomicAdd(&g_den[dst * HV + 0], a.x);
    atomicAdd(&g_den[dst * HV + 1], a.y);
    atomicAdd(&g_den[dst * HV + 2], a.z);
    atomicAdd(&g_den[dst * HV + 3], a.w);
}

// ---------------- CSR aggregation: out[n] = bias + x[n] + sum alpha*xw[src,et] ----------------
__global__ void agg_kernel(const float* __restrict__ xin, float* __restrict__ xout,
                           const float* __restrict__ bias) {
    int n = blockIdx.x;
    int t = threadIdx.x;       // 128 threads, 4 channels each
    int h = t >> 5;            // head index for these channels
    float inv = 1.f / (g_den[n * HV + h] + 1e-16f);
    float4 acc = ((const float4*)bias)[t];
    float4 xr = ((const float4*)(xin + (long)n * CV))[t];
    acc.x += xr.x; acc.y += xr.y; acc.z += xr.z; acc.w += xr.w;
    int b0 = g_off[n], b1 = g_off[n + 1];
    for (int ii = b0; ii < b1; ii++) {
        int e = g_perm[ii];
        float coeff = g_alpha[e * HV + h] * inv;
        const float4* vp = (const float4*)(g_xw + ((long)g_src[e] * RV + g_typ[e]) * CV) + t;
        float4 vv = *vp;
        acc.x = fmaf(coeff, vv.x, acc.x);
        acc.y = fmaf(coeff, vv.y, acc.y);
        acc.z = fmaf(coeff, vv.z, acc.z);
        acc.w = fmaf(coeff, vv.w, acc.w);
    }
    ((float4*)(xout + (long)n * CV))[t] = acc;
}

// ---------------- layernorm (+optional pre-add / post-add) ----------------
__global__ void ln_kernel(const float* __restrict__ in, const float* __restrict__ addpre,
                          const float* __restrict__ addpost, float* __restrict__ out,
                          const float* __restrict__ gamma, const float* __restrict__ beta) {
    int n = blockIdx.x, t = threadIdx.x;
    int lane = t & 31, w = t >> 5;
    __shared__ float sred[4];
    float4 x = ((const float4*)(in + (long)n * CV))[t];
    if (addpre) {
        float4 a = ((const float4*)(addpre + (long)n * CV))[t];
        x.x += a.x; x.y += a.y; x.z += a.z; x.w += a.w;
    }
    float s = x.x + x.y + x.z + x.w;
    s = warp_red(s);
    if (!lane) sred[w] = s;
    __syncthreads();
    float mean = (sred[0] + sred[1] + sred[2] + sred[3]) * (1.f / CV);
    __syncthreads();
    float dx = x.x - mean, dy = x.y - mean, dz = x.z - mean, dw = x.w - mean;
    float ss = dx * dx + dy * dy + dz * dz + dw * dw;
    ss = warp_red(ss);
    if (!lane) sred[w] = ss;
    __syncthreads();
    float var = (sred[0] + sred[1] + sred[2] + sred[3]) * (1.f / CV);
    float rstd = rsqrtf(var + 1e-5f);
    float4 g = ((const float4*)gamma)[t];
    float4 b = ((const float4*)beta)[t];
    float4 o;
    o.x = g.x * dx * rstd + b.x;
    o.y = g.y * dy * rstd + b.y;
    o.z = g.z * dz * rstd + b.z;
    o.w = g.w * dw * rstd + b.w;
    if (addpost) {
        float4 p = ((const float4*)(addpost + (long)n * CV))[t];
        o.x += p.x; o.y += p.y; o.z += p.z; o.w += p.w;
    }
    ((float4*)(out + (long)n * CV))[t] = o;
}

// ---------------- launcher ----------------
extern "C" void kernel_launch(void* const* d_in, const int* in_sizes, int n_in,
                              void* d_out, int out_size) {
    const float* x   = (const float*)d_in[0];
    const void*  ei  = d_in[1];
    const void*  et  = d_in[2];
    const float* eattr = (const float*)d_in[3];
    const float* W   = (const float*)d_in[4];
    const float* qm  = (const float*)d_in[5];
    const float* km  = (const float*)d_in[6];
    const float* em  = (const float*)d_in[7];
    const float* we  = (const float*)d_in[8];
    const float* cb  = (const float*)d_in[9];
    const float* lg  = (const float*)d_in[10];
    const float* lb  = (const float*)d_in[11];
    const float* f1w = (const float*)d_in[12];
    const float* f1b = (const float*)d_in[13];
    const float* f2w = (const float*)d_in[14];
    const float* f2b = (const float*)d_in[15];
    float* out = (float*)d_out;

    float *pxw, *pxA, *pxB, *ph0, *ph1;
    cudaGetSymbolAddress((void**)&pxw, g_xw);
    cudaGetSymbolAddress((void**)&pxA, g_xA);
    cudaGetSymbolAddress((void**)&pxB, g_xB);
    cudaGetSymbolAddress((void**)&ph0, g_h0);
    cudaGetSymbolAddress((void**)&ph1, g_h1);

    const int TB = 256;
    const int EB = (EV + TB - 1) / TB;

    detect_kernel<<<1, 256>>>((const int*)ei, (const int*)et);
    convert_kernel<<<EB, TB>>>(ei, et);
    reset_cnt_kernel<<<(NV + TB - 1) / TB, TB>>>();
    hist_kernel<<<EB, TB>>>();
    scan_kernel<<<1, 1024>>>();
    scatter_kernel<<<EB, TB>>>();

    // edge-attr projections for BOTH layers in one eattr pass
    p_kernel<<<EDV / 8, 256>>>(we, em);
    ae_kernel<<<EV / 8, 256>>>(eattr);

    for (int l = 0; l < LLV; l++) {
        const float* xin = (l == 0) ? x : pxB;
        float* xout = (l == 0) ? pxB : pxA;

        // xw[n,r,:] = xin @ W[l,r]
        dim3 g1(CV / 128, (NV + 127) / 128, RV);
        sgemm_k<0><<<g1, 256>>>(xin, W + (long)l * RV * CV * CV, pxw,
                                NV, CV, CV, CV, CV, RV * CV,
                                (long)CV * CV, (long)CV, nullptr, nullptr);

        qk_kernel<<<NV * RV / 8, 256>>>(qm + l * CV * HV, km + l * CV * HV);
        reset_nodes_kernel<<<(NV * HV + TB - 1) / TB, TB>>>();
        logits_kernel<<<EB, TB>>>(l);
        expsum_kernel<<<EB, TB>>>();
        agg_kernel<<<NV, 128>>>(xin, xout, cb + l * CV);
    }

    // h0 = LN(xA + enc_emb)
    ln_kernel<<<NV, 128>>>(pxA, x, nullptr, ph0, lg, lb);
    // h1 = relu(h0 @ ff1 + b1)
    {
        dim3 g2(2 * CV / 128, (NV + 127) / 128, 1);
        sgemm_k<1><<<g2, 256>>>(ph0, f1w, ph1, NV, 2 * CV, CV,
                                CV, 2 * CV, 2 * CV, 0, 0, f1b, nullptr);
    }
    // h2 = h1 @ ff2 + b2 + h0  (into pxB)
    {
        dim3 g3(CV / 128, (NV + 127) / 128, 1);
        sgemm_k<2><<<g3, 256>>>(ph1, f2w, pxB, NV, CV, 2 * CV,
                                2 * CV, CV, CV, 0, 0, f2b, ph0);
    }
    // out = LN(h2) + enc_emb
    ln_kernel<<<NV, 128>>>(pxB, nullptr, x, out, lg, lb);
}

// round 2
// speedup vs baseline: 1.6755x; 1.6755x over previous
#include <cuda_runtime.h>
#include <math.h>
#include <stdint.h>

#define NV 10000
#define EV 160000
#define CV 512
#define HV 4
#define RV 8
#define LLV 2
#define EDV 768
#define OV 128

// ---------------- scratch (device globals; no cudaMalloc allowed) ----------------
__device__ float g_xw[(size_t)NV * RV * CV];     // 164 MB  [n][r][c]
__device__ float g_xA[NV * CV];
__device__ float g_xB[NV * CV];
__device__ float g_h0[NV * CV];
__device__ float g_h1[NV * 2 * CV];
__device__ float g_Q[NV * RV * HV];
__device__ float g_K[NV * RV * HV];
__device__ float g_P[EDV * LLV * HV];
__device__ float g_ae[(size_t)EV * LLV * HV];
__device__ float g_alpha[EV * HV];
__device__ unsigned g_maxu[NV * HV];
__device__ float g_den[NV * HV];
__device__ int g_src[EV], g_dst[EV], g_typ[EV];
__device__ int g_cnt[NV], g_off[NV + 1], g_cur[NV];
__device__ int g_perm[EV];
__device__ int g_flags[2];

// ---------------- helpers ----------------
__device__ __forceinline__ float warp_red(float v) {
#pragma unroll
    for (int s = 16; s; s >>= 1) v += __shfl_down_sync(0xffffffffu, v, s);
    return v;
}
__device__ __forceinline__ unsigned fenc(float f) {
    unsigned b = __float_as_uint(f);
    return (b & 0x80000000u) ? ~b : (b | 0x80000000u);
}
__device__ __forceinline__ float fdec(unsigned u) {
    return __uint_as_float((u & 0x80000000u) ? (u ^ 0x80000000u) : ~u);
}
__device__ __forceinline__ float tf32r(float f) {
    unsigned u;
    asm("cvt.rna.tf32.f32 %0, %1;" : "=r"(u) : "f"(f));
    return __uint_as_float(u);
}
__device__ __forceinline__ void mma_tf32(float* d, const unsigned* a, const unsigned* b) {
    asm volatile(
        "mma.sync.aligned.m16n8k8.row.col.f32.tf32.tf32.f32 "
        "{%0,%1,%2,%3}, {%4,%5,%6,%7}, {%8,%9}, {%0,%1,%2,%3};"
        : "+f"(d[0]), "+f"(d[1]), "+f"(d[2]), "+f"(d[3])
        : "r"(a[0]), "r"(a[1]), "r"(a[2]), "r"(a[3]), "r"(b[0]), "r"(b[1]));
}

// ---------------- edge index dtype detection + conversion ----------------
__global__ void detect_kernel(const int* __restrict__ a, const int* __restrict__ b) {
    __shared__ int nz[2];
    if (threadIdx.x < 2) nz[threadIdx.x] = 0;
    __syncthreads();
    int i = threadIdx.x;
    if (a[2 * i + 1] != 0) atomicAdd(&nz[0], 1);
    if (b[2 * i + 1] != 0) atomicAdd(&nz[1], 1);
    __syncthreads();
    if (threadIdx.x == 0) { g_flags[0] = (nz[0] == 0); g_flags[1] = (nz[1] == 0); }
}

__global__ void convert_kernel(const void* __restrict__ ei, const void* __restrict__ et) {
    int e = blockIdx.x * blockDim.x + threadIdx.x;
    if (e >= EV) return;
    int f0 = g_flags[0], f1 = g_flags[1];
    int s, d, t;
    if (f0) {
        const long long* a = (const long long*)ei;
        s = (int)a[e]; d = (int)a[EV + e];
    } else {
        const int* a = (const int*)ei;
        s = a[e]; d = a[EV + e];
    }
    if (f1) t = (int)((const long long*)et)[e];
    else    t = ((const int*)et)[e];
    g_src[e] = s; g_dst[e] = d; g_typ[e] = t;
}

// ---------------- CSR build ----------------
__global__ void reset_cnt_kernel() {
    int i = blockIdx.x * blockDim.x + threadIdx.x;
    if (i < NV) g_cnt[i] = 0;
}
__global__ void hist_kernel() {
    int e = blockIdx.x * blockDim.x + threadIdx.x;
    if (e < EV) atomicAdd(&g_cnt[g_dst[e]], 1);
}
__global__ void scan_kernel() {
    __shared__ int sh[1024];
    __shared__ int carry;
    int t = threadIdx.x;
    if (t == 0) carry = 0;
    __syncthreads();
    for (int base = 0; base < NV; base += 1024) {
        int i = base + t;
        int v = (i < NV) ? g_cnt[i] : 0;
        sh[t] = v;
        __syncthreads();
        for (int s = 1; s < 1024; s <<= 1) {
            int add = (t >= s) ? sh[t - s] : 0;
            __syncthreads();
            sh[t] += add;
            __syncthreads();
        }
        int excl = sh[t] - v + carry;
        if (i < NV) { g_off[i] = excl; g_cur[i] = excl; }
        int tot = sh[1023];
        __syncthreads();
        if (t == 0) carry += tot;
        __syncthreads();
    }
    if (threadIdx.x == 0) g_off[NV] = carry;
}
__global__ void scatter_kernel() {
    int e = blockIdx.x * blockDim.x + threadIdx.x;
    if (e >= EV) return;
    int d = g_dst[e];
    int p = atomicAdd(&g_cur[d], 1);
    g_perm[p] = e;
}

// ---------------- TF32 tensor-core GEMM ----------------
// C[m, n (+ z*cz)] = A[m,:] @ B(z)[:, n]; EPI: 0 none, 1 bias+relu, 2 bias+residual
// Block tile 128x128, BK=16, 8 warps, warp tile 64x32 (wm 0..1, wn 0..3).
template <int EPI>
__global__ __launch_bounds__(256)
void tgemm_k(const float* __restrict__ A, const float* __restrict__ B,
             float* __restrict__ C, int M, int Nc, int K,
             int lda, int ldb, int ldc, long bz, long cz,
             const float* __restrict__ bias, const float* __restrict__ res) {
    B += (long)blockIdx.z * bz;
    C += (long)blockIdx.z * cz;
    __shared__ float As[2][16][136];   // [k][m], stride 136 -> bank = (8k+m)&31
    __shared__ float Bs[2][16][136];   // [k][n]

    const int tid = threadIdx.x;
    const int warp = tid >> 5, lane = tid & 31;
    const int wm = warp >> 2, wn = warp & 3;
    const int g = lane >> 2, c = lane & 3;
    const int m0 = blockIdx.y * 128, n0 = blockIdx.x * 128;

    // A tile loader mapping: row am (0..127), two float4 cols
    const int am = tid & 127;
    const int ak = tid >> 7;               // 0/1 -> float4 col = ak*2 + i
    const bool arow_ok = (m0 + am) < M;
    // B tile loader mapping: row bk (0..15), float4 cols bcq + 16*i
    const int bk = tid >> 4, bcq = tid & 15;

    float acc[4][4][4];
#pragma unroll
    for (int i = 0; i < 4; i++)
#pragma unroll
        for (int j = 0; j < 4; j++)
#pragma unroll
            for (int q = 0; q < 4; q++) acc[i][j][q] = 0.f;

    const float* Aptr = A + (long)(m0 + am) * lda;
    const float* Bptr = B + (long)bk * ldb + n0;

    const int KT = K >> 4;

    // prologue: stage 0
    {
#pragma unroll
        for (int i = 0; i < 2; i++) {
            int kq = ak * 2 + i;
            float4 a4 = make_float4(0.f, 0.f, 0.f, 0.f);
            if (arow_ok) a4 = *(const float4*)(Aptr + kq * 4);
            As[0][kq * 4 + 0][am] = tf32r(a4.x);
            As[0][kq * 4 + 1][am] = tf32r(a4.y);
            As[0][kq * 4 + 2][am] = tf32r(a4.z);
            As[0][kq * 4 + 3][am] = tf32r(a4.w);
        }
#pragma unroll
        for (int i = 0; i < 2; i++) {
            int cq = bcq + 16 * i;
            float4 b4 = *(const float4*)(Bptr + cq * 4);
            Bs[0][bk][cq * 4 + 0] = tf32r(b4.x);
            Bs[0][bk][cq * 4 + 1] = tf32r(b4.y);
            Bs[0][bk][cq * 4 + 2] = tf32r(b4.z);
            Bs[0][bk][cq * 4 + 3] = tf32r(b4.w);
        }
    }
    __syncthreads();

    for (int kt = 0; kt < KT; kt++) {
        int buf = kt & 1;
        float4 pa[2], pb[2];
        bool pf = (kt + 1 < KT);
        if (pf) {
#pragma unroll
            for (int i = 0; i < 2; i++) {
                int kq = ak * 2 + i;
                pa[i] = make_float4(0.f, 0.f, 0.f, 0.f);
                if (arow_ok) pa[i] = *(const float4*)(Aptr + (kt + 1) * 16 + kq * 4);
            }
#pragma unroll
            for (int i = 0; i < 2; i++) {
                int cq = bcq + 16 * i;
                pb[i] = *(const float4*)(Bptr + (long)(kt + 1) * 16 * ldb + cq * 4);
            }
        }

#pragma unroll
        for (int ks = 0; ks < 2; ks++) {
            unsigned af[4][4], bf[4][2];
#pragma unroll
            for (int mt = 0; mt < 4; mt++) {
                int mr = wm * 64 + mt * 16;
                af[mt][0] = __float_as_uint(As[buf][ks * 8 + c][mr + g]);
                af[mt][1] = __float_as_uint(As[buf][ks * 8 + c][mr + g + 8]);
                af[mt][2] = __float_as_uint(As[buf][ks * 8 + c + 4][mr + g]);
                af[mt][3] = __float_as_uint(As[buf][ks * 8 + c + 4][mr + g + 8]);
            }
#pragma unroll
            for (int nt = 0; nt < 4; nt++) {
                int nc = wn * 32 + nt * 8;
                bf[nt][0] = __float_as_uint(Bs[buf][ks * 8 + c][nc + g]);
                bf[nt][1] = __float_as_uint(Bs[buf][ks * 8 + c + 4][nc + g]);
            }
#pragma unroll
            for (int mt = 0; mt < 4; mt++)
#pragma unroll
                for (int nt = 0; nt < 4; nt++)
                    mma_tf32(acc[mt][nt], af[mt], bf[nt]);
        }

        if (pf) {
            int nb = buf ^ 1;
#pragma unroll
            for (int i = 0; i < 2; i++) {
                int kq = ak * 2 + i;
                As[nb][kq * 4 + 0][am] = tf32r(pa[i].x);
                As[nb][kq * 4 + 1][am] = tf32r(pa[i].y);
                As[nb][kq * 4 + 2][am] = tf32r(pa[i].z);
                As[nb][kq * 4 + 3][am] = tf32r(pa[i].w);
            }
#pragma unroll
            for (int i = 0; i < 2; i++) {
                int cq = bcq + 16 * i;
                Bs[nb][bk][cq * 4 + 0] = tf32r(pb[i].x);
                Bs[nb][bk][cq * 4 + 1] = tf32r(pb[i].y);
                Bs[nb][bk][cq * 4 + 2] = tf32r(pb[i].z);
                Bs[nb][bk][cq * 4 + 3] = tf32r(pb[i].w);
            }
        }
        __syncthreads();
    }

    // epilogue
#pragma unroll
    for (int mt = 0; mt < 4; mt++) {
#pragma unroll
        for (int half = 0; half < 2; half++) {
            int m = m0 + wm * 64 + mt * 16 + g + half * 8;
            if (m >= M) continue;
#pragma unroll
            for (int nt = 0; nt < 4; nt++) {
                int n = n0 + wn * 32 + nt * 8 + 2 * c;
                float v0 = acc[mt][nt][half * 2 + 0];
                float v1 = acc[mt][nt][half * 2 + 1];
                if (EPI == 1) {
                    v0 = fmaxf(v0 + bias[n], 0.f);
                    v1 = fmaxf(v1 + bias[n + 1], 0.f);
                } else if (EPI == 2) {
                    v0 = v0 + bias[n] + res[(long)m * Nc + n];
                    v1 = v1 + bias[n + 1] + res[(long)m * Nc + n + 1];
                }
                float2 o = make_float2(v0, v1);
                *(float2*)(C + (long)m * ldc + n) = o;
            }
        }
    }
}

// ---------------- Q/K projection from xw: one warp per (n,r) row ----------------
__global__ void qk_kernel(const float* __restrict__ qm, const float* __restrict__ km) {
    int rr = blockIdx.x * 8 + (threadIdx.x >> 5);
    int lane = threadIdx.x & 31;
    const float* row = g_xw + (long)rr * CV;
    float qa0 = 0, qa1 = 0, qa2 = 0, qa3 = 0;
    float ka0 = 0, ka1 = 0, ka2 = 0, ka3 = 0;
#pragma unroll
    for (int j = 0; j < 16; j++) {
        int c = lane + 32 * j;
        float v = row[c];
        float4 q4 = *(const float4*)(qm + c * HV);
        float4 k4 = *(const float4*)(km + c * HV);
        qa0 = fmaf(v, q4.x, qa0); qa1 = fmaf(v, q4.y, qa1);
        qa2 = fmaf(v, q4.z, qa2); qa3 = fmaf(v, q4.w, qa3);
        ka0 = fmaf(v, k4.x, ka0); ka1 = fmaf(v, k4.y, ka1);
        ka2 = fmaf(v, k4.z, ka2); ka3 = fmaf(v, k4.w, ka3);
    }
    qa0 = warp_red(qa0); qa1 = warp_red(qa1); qa2 = warp_red(qa2); qa3 = warp_red(qa3);
    ka0 = warp_red(ka0); ka1 = warp_red(ka1); ka2 = warp_red(ka2); ka3 = warp_red(ka3);
    if (lane == 0) {
        *(float4*)(g_Q + (long)rr * HV) = make_float4(qa0, qa1, qa2, qa3);
        *(float4*)(g_K + (long)rr * HV) = make_float4(ka0, ka1, ka2, ka3);
    }
}

// ---------------- P = We @ e, both layers ----------------
__global__ void p_kernel(const float* __restrict__ we, const float* __restrict__ ev) {
    int j = blockIdx.x * 8 + (threadIdx.x >> 5);
    int lane = threadIdx.x & 31;
    float a[8];
#pragma unroll
    for (int u = 0; u < 8; u++) a[u] = 0.f;
#pragma unroll
    for (int jj = 0; jj < 16; jj++) {
        int c = lane + 32 * jj;
        float w0 = we[(long)j * CV + c];
        float w1 = we[(long)EDV * CV + (long)j * CV + c];
        float4 e0 = *(const float4*)(ev + c * HV);
        float4 e1 = *(const float4*)(ev + CV * HV + c * HV);
        a[0] = fmaf(w0, e0.x, a[0]); a[1] = fmaf(w0, e0.y, a[1]);
        a[2] = fmaf(w0, e0.z, a[2]); a[3] = fmaf(w0, e0.w, a[3]);
        a[4] = fmaf(w1, e1.x, a[4]); a[5] = fmaf(w1, e1.y, a[5]);
        a[6] = fmaf(w1, e1.z, a[6]); a[7] = fmaf(w1, e1.w, a[7]);
    }
#pragma unroll
    for (int u = 0; u < 8; u++) a[u] = warp_red(a[u]);
    if (lane == 0) {
        *(float4*)(g_P + j * 8) = make_float4(a[0], a[1], a[2], a[3]);
        *(float4*)(g_P + j * 8 + 4) = make_float4(a[4], a[5], a[6], a[7]);
    }
}

// ---------------- ae = eattr @ P, both layers ----------------
__global__ void ae_kernel(const float* __restrict__ eattr) {
    int e = blockIdx.x * 8 + (threadIdx.x >> 5);
    int lane = threadIdx.x & 31;
    float a[8];
#pragma unroll
    for (int u = 0; u < 8; u++) a[u] = 0.f;
#pragma unroll
    for (int jj = 0; jj < 24; jj++) {
        int j = lane + 32 * jj;
        float v = eattr[(long)e * EDV + j];
        float4 p0 = *(const float4*)(g_P + j * 8);
        float4 p1 = *(const float4*)(g_P + j * 8 + 4);
        a[0] = fmaf(v, p0.x, a[0]); a[1] = fmaf(v, p0.y, a[1]);
        a[2] = fmaf(v, p0.z, a[2]); a[3] = fmaf(v, p0.w, a[3]);
        a[4] = fmaf(v, p1.x, a[4]); a[5] = fmaf(v, p1.y, a[5]);
        a[6] = fmaf(v, p1.z, a[6]); a[7] = fmaf(v, p1.w, a[7]);
    }
#pragma unroll
    for (int u = 0; u < 8; u++) a[u] = warp_red(a[u]);
    if (lane == 0) {
        *(float4*)(g_ae + (long)e * 8) = make_float4(a[0], a[1], a[2], a[3]);
        *(float4*)(g_ae + (long)e * 8 + 4) = make_float4(a[4], a[5], a[6], a[7]);
    }
}

// ---------------- per-layer reset of softmax state ----------------
__global__ void reset_nodes_kernel() {
    int i = blockIdx.x * blockDim.x + threadIdx.x;
    if (i < NV * HV) { g_maxu[i] = 0u; g_den[i] = 0.f; }
}

// ---------------- attention logits + leaky_relu + segment max ----------------
__global__ void logits_kernel(int l) {
    int e = blockIdx.x * blockDim.x + threadIdx.x;
    if (e >= EV) return;
    int dst = g_dst[e], src = g_src[e], t = g_typ[e];
    float4 ae = *(const float4*)(g_ae + (long)e * (LLV * HV) + l * HV);
    float4 qv = *(const float4*)(g_Q + (long)(dst * RV + t) * HV);
    float4 kv = *(const float4*)(g_K + (long)(src * RV + t) * HV);
    float4 a;
    a.x = qv.x + kv.x + ae.x; a.x = a.x > 0.f ? a.x : 0.2f * a.x;
    a.y = qv.y + kv.y + ae.y; a.y = a.y > 0.f ? a.y : 0.2f * a.y;
    a.z = qv.z + kv.z + ae.z; a.z = a.z > 0.f ? a.z : 0.2f * a.z;
    a.w = qv.w + kv.w + ae.w; a.w = a.w > 0.f ? a.w : 0.2f * a.w;
    *(float4*)(g_alpha + (long)e * HV) = a;
    atomicMax(&g_maxu[dst * HV + 0], fenc(a.x));
    atomicMax(&g_maxu[dst * HV + 1], fenc(a.y));
    atomicMax(&g_maxu[dst * HV + 2], fenc(a.z));
    atomicMax(&g_maxu[dst * HV + 3], fenc(a.w));
}

// ---------------- exp + segment sum ----------------
__global__ void expsum_kernel() {
    int e = blockIdx.x * blockDim.x + threadIdx.x;
    if (e >= EV) return;
    int dst = g_dst[e];
    float4 a = *(const float4*)(g_alpha + (long)e * HV);
    a.x = expf(a.x - fdec(g_maxu[dst * HV + 0]));
    a.y = expf(a.y - fdec(g_maxu[dst * HV + 1]));
    a.z = expf(a.z - fdec(g_maxu[dst * HV + 2]));
    a.w = expf(a.w - fdec(g_maxu[dst * HV + 3]));
    *(float4*)(g_alpha + (long)e * HV) = a;
    atomicAdd(&g_den[dst * HV + 0], a.x);
    atomicAdd(&g_den[dst * HV + 1], a.y);
    atomicAdd(&g_den[dst * HV + 2], a.z);
    atomicAdd(&g_den[dst * HV + 3], a.w);
}

// ---------------- CSR aggregation ----------------
__global__ void agg_kernel(const float* __restrict__ xin, float* __restrict__ xout,
                           const float* __restrict__ bias) {
    int n = blockIdx.x;
    int t = threadIdx.x;
    int h = t >> 5;
    float inv = 1.f / (g_den[n * HV + h] + 1e-16f);
    float4 acc = ((const float4*)bias)[t];
    float4 xr = ((const float4*)(xin + (long)n * CV))[t];
    acc.x += xr.x; acc.y += xr.y; acc.z += xr.z; acc.w += xr.w;
    int b0 = g_off[n], b1 = g_off[n + 1];
    for (int ii = b0; ii < b1; ii++) {
        int e = g_perm[ii];
        float coeff = g_alpha[e * HV + h] * inv;
        const float4* vp = (const float4*)(g_xw + ((long)g_src[e] * RV + g_typ[e]) * CV) + t;
        float4 vv = *vp;
        acc.x = fmaf(coeff, vv.x, acc.x);
        acc.y = fmaf(coeff, vv.y, acc.y);
        acc.z = fmaf(coeff, vv.z, acc.z);
        acc.w = fmaf(coeff, vv.w, acc.w);
    }
    ((float4*)(xout + (long)n * CV))[t] = acc;
}

// ---------------- layernorm ----------------
__global__ void ln_kernel(const float* __restrict__ in, const float* __restrict__ addpre,
                          const float* __restrict__ addpost, float* __restrict__ out,
                          const float* __restrict__ gamma, const float* __restrict__ beta) {
    int n = blockIdx.x, t = threadIdx.x;
    int lane = t & 31, w = t >> 5;
    __shared__ float sred[4];
    float4 x = ((const float4*)(in + (long)n * CV))[t];
    if (addpre) {
        float4 a = ((const float4*)(addpre + (long)n * CV))[t];
        x.x += a.x; x.y += a.y; x.z += a.z; x.w += a.w;
    }
    float s = x.x + x.y + x.z + x.w;
    s = warp_red(s);
    if (!lane) sred[w] = s;
    __syncthreads();
    float mean = (sred[0] + sred[1] + sred[2] + sred[3]) * (1.f / CV);
    __syncthreads();
    float dx = x.x - mean, dy = x.y - mean, dz = x.z - mean, dw = x.w - mean;
    float ss = dx * dx + dy * dy + dz * dz + dw * dw;
    ss = warp_red(ss);
    if (!lane) sred[w] = ss;
    __syncthreads();
    float var = (sred[0] + sred[1] + sred[2] + sred[3]) * (1.f / CV);
    float rstd = rsqrtf(var + 1e-5f);
    float4 g = ((const float4*)gamma)[t];
    float4 b = ((const float4*)beta)[t];
    float4 o;
    o.x = g.x * dx * rstd + b.x;
    o.y = g.y * dy * rstd + b.y;
    o.z = g.z * dz * rstd + b.z;
    o.w = g.w * dw * rstd + b.w;
    if (addpost) {
        float4 p = ((const float4*)(addpost + (long)n * CV))[t];
        o.x += p.x; o.y += p.y; o.z += p.z; o.w += p.w;
    }
    ((float4*)(out + (long)n * CV))[t] = o;
}

// ---------------- launcher ----------------
extern "C" void kernel_launch(void* const* d_in, const int* in_sizes, int n_in,
                              void* d_out, int out_size) {
    const float* x   = (const float*)d_in[0];
    const void*  ei  = d_in[1];
    const void*  et  = d_in[2];
    const float* eattr = (const float*)d_in[3];
    const float* W   = (const float*)d_in[4];
    const float* qm  = (const float*)d_in[5];
    const float* km  = (const float*)d_in[6];
    const float* em  = (const float*)d_in[7];
    const float* we  = (const float*)d_in[8];
    const float* cb  = (const float*)d_in[9];
    const float* lg  = (const float*)d_in[10];
    const float* lb  = (const float*)d_in[11];
    const float* f1w = (const float*)d_in[12];
    const float* f1b = (const float*)d_in[13];
    const float* f2w = (const float*)d_in[14];
    const float* f2b = (const float*)d_in[15];
    float* out = (float*)d_out;

    float *pxw, *pxA, *pxB, *ph0, *ph1;
    cudaGetSymbolAddress((void**)&pxw, g_xw);
    cudaGetSymbolAddress((void**)&pxA, g_xA);
    cudaGetSymbolAddress((void**)&pxB, g_xB);
    cudaGetSymbolAddress((void**)&ph0, g_h0);
    cudaGetSymbolAddress((void**)&ph1, g_h1);

    const int TB = 256;
    const int EB = (EV + TB - 1) / TB;

    detect_kernel<<<1, 256>>>((const int*)ei, (const int*)et);
    convert_kernel<<<EB, TB>>>(ei, et);
    reset_cnt_kernel<<<(NV + TB - 1) / TB, TB>>>();
    hist_kernel<<<EB, TB>>>();
    scan_kernel<<<1, 1024>>>();
    scatter_kernel<<<EB, TB>>>();

    // edge-attr projections for BOTH layers in one eattr pass
    p_kernel<<<EDV / 8, 256>>>(we, em);
    ae_kernel<<<EV / 8, 256>>>(eattr);

    for (int l = 0; l < LLV; l++) {
        const float* xin = (l == 0) ? x : pxB;
        float* xout = (l == 0) ? pxB : pxA;

        // xw[n,r,:] = xin @ W[l,r]   (TF32 tensor cores)
        dim3 g1(CV / 128, (NV + 127) / 128, RV);
        tgemm_k<0><<<g1, 256>>>(xin, W + (long)l * RV * CV * CV, pxw,
                                NV, CV, CV, CV, CV, RV * CV,
                                (long)CV * CV, (long)CV, nullptr, nullptr);

        qk_kernel<<<NV * RV / 8, 256>>>(qm + l * CV * HV, km + l * CV * HV);
        reset_nodes_kernel<<<(NV * HV + TB - 1) / TB, TB>>>();
        logits_kernel<<<EB, TB>>>(l);
        expsum_kernel<<<EB, TB>>>();
        agg_kernel<<<NV, 128>>>(xin, xout, cb + l * CV);
    }

    // h0 = LN(xA + enc_emb)
    ln_kernel<<<NV, 128>>>(pxA, x, nullptr, ph0, lg, lb);
    // h1 = relu(h0 @ ff1 + b1)
    {
        dim3 g2(2 * CV / 128, (NV + 127) / 128, 1);
        tgemm_k<1><<<g2, 256>>>(ph0, f1w, ph1, NV, 2 * CV, CV,
                                CV, 2 * CV, 2 * CV, 0, 0, f1b, nullptr);
    }
    // h2 = h1 @ ff2 + b2 + h0  (into pxB)
    {
        dim3 g3(CV / 128, (NV + 127) / 128, 1);
        tgemm_k<2><<<g3, 256>>>(ph1, f2w, pxB, NV, CV, 2 * CV,
                                2 * CV, CV, CV, 0, 0, f2b, ph0);
    }
    // out = LN(h2) + enc_emb
    ln_kernel<<<NV, 128>>>(pxB, nullptr, x, out, lg, lb);
}

// round 3
// speedup vs baseline: 2.1136x; 1.2615x over previous
#include <cuda_runtime.h>
#include <math.h>
#include <stdint.h>

#define NV 10000
#define EV 160000
#define CV 512
#define HV 4
#define RV 8
#define LLV 2
#define EDV 768
#define OV 128

// ---------------- scratch (device globals; no cudaMalloc allowed) ----------------
__device__ float g_xw[(size_t)NV * RV * CV];     // 164 MB  [n][r][c]
__device__ float g_xA[NV * CV];
__device__ float g_xB[NV * CV];
__device__ float g_h0[NV * CV];
__device__ float g_h1[NV * 2 * CV];
__device__ float g_xt[NV * CV];                  // tf32-rounded activations
__device__ float g_h0t[NV * CV];
__device__ float g_Wt[(size_t)LLV * RV * CV * CV];  // tf32-rounded weights
__device__ float g_f1t[CV * 2 * CV];
__device__ float g_f2t[2 * CV * CV];
__device__ float g_Wqk[LLV * CV * 64];           // [l][c][ 0..31: q(r*4+h) | 32..63: k ]
__device__ float g_QK[NV * 64];
__device__ float g_P[EDV * LLV * HV];
__device__ float g_ae[(size_t)EV * LLV * HV];
__device__ float g_alpha[EV * HV];
__device__ unsigned g_maxu[NV * HV];
__device__ float g_den[NV * HV];
__device__ int g_src[EV], g_dst[EV], g_typ[EV];
__device__ int g_cnt[NV], g_off[NV + 1], g_cur[NV];
__device__ int g_perm[EV];
__device__ int g_flags[2];

// ---------------- helpers ----------------
__device__ __forceinline__ float warp_red(float v) {
#pragma unroll
    for (int s = 16; s; s >>= 1) v += __shfl_down_sync(0xffffffffu, v, s);
    return v;
}
__device__ __forceinline__ unsigned fenc(float f) {
    unsigned b = __float_as_uint(f);
    return (b & 0x80000000u) ? ~b : (b | 0x80000000u);
}
__device__ __forceinline__ float fdec(unsigned u) {
    return __uint_as_float((u & 0x80000000u) ? (u ^ 0x80000000u) : ~u);
}
__device__ __forceinline__ float tf32r(float f) {
    unsigned u;
    asm("cvt.rna.tf32.f32 %0, %1;" : "=r"(u) : "f"(f));
    return __uint_as_float(u);
}
__device__ __forceinline__ void mma_tf32(float* d, const unsigned* a, const unsigned* b) {
    asm volatile(
        "mma.sync.aligned.m16n8k8.row.col.f32.tf32.tf32.f32 "
        "{%0,%1,%2,%3}, {%4,%5,%6,%7}, {%8,%9}, {%0,%1,%2,%3};"
        : "+f"(d[0]), "+f"(d[1]), "+f"(d[2]), "+f"(d[3])
        : "r"(a[0]), "r"(a[1]), "r"(a[2]), "r"(a[3]), "r"(b[0]), "r"(b[1]));
}
__device__ __forceinline__ void cp16(uint32_t dst, const void* src, bool p) {
    int sz = p ? 16 : 0;
    asm volatile("cp.async.cg.shared.global [%0], [%1], 16, %2;\n"
                 :: "r"(dst), "l"(src), "r"(sz));
}

// ---------------- edge index dtype detection + conversion ----------------
__global__ void detect_kernel(const int* __restrict__ a, const int* __restrict__ b) {
    __shared__ int nz[2];
    if (threadIdx.x < 2) nz[threadIdx.x] = 0;
    __syncthreads();
    int i = threadIdx.x;
    if (a[2 * i + 1] != 0) atomicAdd(&nz[0], 1);
    if (b[2 * i + 1] != 0) atomicAdd(&nz[1], 1);
    __syncthreads();
    if (threadIdx.x == 0) { g_flags[0] = (nz[0] == 0); g_flags[1] = (nz[1] == 0); }
}

__global__ void convert_kernel(const void* __restrict__ ei, const void* __restrict__ et) {
    int e = blockIdx.x * blockDim.x + threadIdx.x;
    if (e >= EV) return;
    int f0 = g_flags[0], f1 = g_flags[1];
    int s, d, t;
    if (f0) {
        const long long* a = (const long long*)ei;
        s = (int)a[e]; d = (int)a[EV + e];
    } else {
        const int* a = (const int*)ei;
        s = a[e]; d = a[EV + e];
    }
    if (f1) t = (int)((const long long*)et)[e];
    else    t = ((const int*)et)[e];
    g_src[e] = s; g_dst[e] = d; g_typ[e] = t;
}

// ---------------- CSR build ----------------
__global__ void reset_cnt_kernel() {
    int i = blockIdx.x * blockDim.x + threadIdx.x;
    if (i < NV) g_cnt[i] = 0;
}
__global__ void hist_kernel() {
    int e = blockIdx.x * blockDim.x + threadIdx.x;
    if (e < EV) atomicAdd(&g_cnt[g_dst[e]], 1);
}
__global__ void scan_kernel() {
    __shared__ int sh[1024];
    __shared__ int carry;
    int t = threadIdx.x;
    if (t == 0) carry = 0;
    __syncthreads();
    for (int base = 0; base < NV; base += 1024) {
        int i = base + t;
        int v = (i < NV) ? g_cnt[i] : 0;
        sh[t] = v;
        __syncthreads();
        for (int s = 1; s < 1024; s <<= 1) {
            int add = (t >= s) ? sh[t - s] : 0;
            __syncthreads();
            sh[t] += add;
            __syncthreads();
        }
        int excl = sh[t] - v + carry;
        if (i < NV) { g_off[i] = excl; g_cur[i] = excl; }
        int tot = sh[1023];
        __syncthreads();
        if (t == 0) carry += tot;
        __syncthreads();
    }
    if (threadIdx.x == 0) g_off[NV] = carry;
}
__global__ void scatter_kernel() {
    int e = blockIdx.x * blockDim.x + threadIdx.x;
    if (e >= EV) return;
    int d = g_dst[e];
    int p = atomicAdd(&g_cur[d], 1);
    g_perm[p] = e;
}

// ---------------- elementwise tf32 rounding ----------------
__global__ void cvt_kernel(const float* __restrict__ in, float* __restrict__ out, int n4) {
    int i = blockIdx.x * blockDim.x + threadIdx.x;
    if (i >= n4) return;
    float4 v = ((const float4*)in)[i];
    v.x = tf32r(v.x); v.y = tf32r(v.y); v.z = tf32r(v.z); v.w = tf32r(v.w);
    ((float4*)out)[i] = v;
}

// ---------------- Wqk[l][c][*] = [ W[l,r]@q | W[l,r]@k ]  (tf32-rounded) ----------------
__global__ void wqk_kernel(const float* __restrict__ W, const float* __restrict__ q,
                           const float* __restrict__ k) {
    int l = blockIdx.x >> 3, r = blockIdx.x & 7;
    __shared__ float sq[CV * HV], sk[CV * HV];
    for (int i = threadIdx.x; i < CV * HV; i += 256) {
        sq[i] = q[(long)l * CV * HV + i];
        sk[i] = k[(long)l * CV * HV + i];
    }
    __syncthreads();
#pragma unroll
    for (int rep = 0; rep < 2; rep++) {
        int cc = threadIdx.x + rep * 256;
        const float* wrow = W + (((long)l * RV + r) * CV + cc) * CV;
        float aq[HV] = {0, 0, 0, 0}, ak[HV] = {0, 0, 0, 0};
        for (int d = 0; d < CV; d += 4) {
            float4 w4 = *(const float4*)(wrow + d);
            const float* wv = &w4.x;
#pragma unroll
            for (int u = 0; u < 4; u++) {
                float w = wv[u];
                const float* qd = sq + (d + u) * HV;
                const float* kd = sk + (d + u) * HV;
                aq[0] = fmaf(w, qd[0], aq[0]); aq[1] = fmaf(w, qd[1], aq[1]);
                aq[2] = fmaf(w, qd[2], aq[2]); aq[3] = fmaf(w, qd[3], aq[3]);
                ak[0] = fmaf(w, kd[0], ak[0]); ak[1] = fmaf(w, kd[1], ak[1]);
                ak[2] = fmaf(w, kd[2], ak[2]); ak[3] = fmaf(w, kd[3], ak[3]);
            }
        }
        float* o = g_Wqk + ((long)l * CV + cc) * 64;
#pragma unroll
        for (int h = 0; h < HV; h++) {
            o[r * 4 + h] = tf32r(aq[h]);
            o[32 + r * 4 + h] = tf32r(ak[h]);
        }
    }
}

// ---------------- TF32 GEMM, cp.async double-buffered ----------------
// C[m, n (+z*cz)] = A[m,:] @ B(z)[:,n]; EPI: 0 none, 1 bias+relu(+tf32 round), 2 bias+residual
template <int EPI>
__global__ __launch_bounds__(256)
void tgemm_k(const float* __restrict__ A, const float* __restrict__ B,
             float* __restrict__ C, int M, int Nc, int K,
             int lda, int ldb, int ldc, long bz, long cz,
             const float* __restrict__ bias, const float* __restrict__ res) {
    B += (long)blockIdx.z * bz;
    C += (long)blockIdx.z * cz;
    __shared__ __align__(16) float As[2][128][20];   // [m][k], stride 20 -> conflict-free frags
    __shared__ __align__(16) float Bs[2][16][136];   // [k][n], stride 136

    const int tid = threadIdx.x;
    const int warp = tid >> 5, lane = tid & 31;
    const int wm = warp >> 2, wn = warp & 3;
    const int g = lane >> 2, c = lane & 3;
    const int m0 = blockIdx.y * 128, n0 = blockIdx.x * 128;

    const int arow = tid >> 2, ac4 = tid & 3;   // + i*64 rows
    const int brow = tid >> 5, bcol = (tid & 31) * 4;  // + i*8 rows

    uint32_t sA = (uint32_t)__cvta_generic_to_shared(&As[0][0][0]);
    uint32_t sB = (uint32_t)__cvta_generic_to_shared(&Bs[0][0][0]);

    float acc[4][4][4];
#pragma unroll
    for (int i = 0; i < 4; i++)
#pragma unroll
        for (int j = 0; j < 4; j++)
#pragma unroll
            for (int qq = 0; qq < 4; qq++) acc[i][j][qq] = 0.f;

    const int KT = K >> 4;

#define LOAD_STAGE(s, kt)                                                              \
    {                                                                                  \
        _Pragma("unroll")                                                              \
        for (int i = 0; i < 2; i++) {                                                  \
            int r = arow + i * 64;                                                     \
            bool p = (m0 + r) < M;                                                     \
            const float* gp = A + (long)(m0 + r) * lda + (kt) * 16 + ac4 * 4;          \
            cp16(sA + (((s) * 128 + r) * 20 + ac4 * 4) * 4, gp, p);                    \
        }                                                                              \
        _Pragma("unroll")                                                              \
        for (int i = 0; i < 2; i++) {                                                  \
            int r = brow + i * 8;                                                      \
            bool p = (n0 + bcol) < Nc;                                                 \
            const float* gp = B + (long)((kt) * 16 + r) * ldb + n0 + bcol;             \
            cp16(sB + (((s) * 16 + r) * 136 + bcol) * 4, gp, p);                       \
        }                                                                              \
        asm volatile("cp.async.commit_group;\n");                                      \
    }

    LOAD_STAGE(0, 0);

    for (int kt = 0; kt < KT; kt++) {
        asm volatile("cp.async.wait_group 0;\n");
        __syncthreads();
        if (kt + 1 < KT) LOAD_STAGE((kt + 1) & 1, kt + 1);
        int buf = kt & 1;
#pragma unroll
        for (int ks = 0; ks < 2; ks++) {
            int k0 = ks * 8;
            unsigned af[4][4], bf[4][2];
#pragma unroll
            for (int mt = 0; mt < 4; mt++) {
                int mr = wm * 64 + mt * 16;
                af[mt][0] = __float_as_uint(As[buf][mr + g][k0 + c]);
                af[mt][1] = __float_as_uint(As[buf][mr + g + 8][k0 + c]);
                af[mt][2] = __float_as_uint(As[buf][mr + g][k0 + c + 4]);
                af[mt][3] = __float_as_uint(As[buf][mr + g + 8][k0 + c + 4]);
            }
#pragma unroll
            for (int nt = 0; nt < 4; nt++) {
                int nc = wn * 32 + nt * 8;
                bf[nt][0] = __float_as_uint(Bs[buf][k0 + c][nc + g]);
                bf[nt][1] = __float_as_uint(Bs[buf][k0 + c + 4][nc + g]);
            }
#pragma unroll
            for (int mt = 0; mt < 4; mt++)
#pragma unroll
                for (int nt = 0; nt < 4; nt++)
                    mma_tf32(acc[mt][nt], af[mt], bf[nt]);
        }
    }
#undef LOAD_STAGE

    // epilogue
#pragma unroll
    for (int mt = 0; mt < 4; mt++) {
#pragma unroll
        for (int half = 0; half < 2; half++) {
            int m = m0 + wm * 64 + mt * 16 + g + half * 8;
            if (m >= M) continue;
#pragma unroll
            for (int nt = 0; nt < 4; nt++) {
                int n = n0 + wn * 32 + nt * 8 + 2 * c;
                if (n >= Nc) continue;
                float v0 = acc[mt][nt][half * 2 + 0];
                float v1 = acc[mt][nt][half * 2 + 1];
                if (EPI == 1) {
                    v0 = tf32r(fmaxf(v0 + bias[n], 0.f));
                    v1 = tf32r(fmaxf(v1 + bias[n + 1], 0.f));
                } else if (EPI == 2) {
                    v0 = v0 + bias[n] + res[(long)m * Nc + n];
                    v1 = v1 + bias[n + 1] + res[(long)m * Nc + n + 1];
                }
                *(float2*)(C + (long)m * ldc + n) = make_float2(v0, v1);
            }
        }
    }
}

// ---------------- P = We @ e, both layers ----------------
__global__ void p_kernel(const float* __restrict__ we, const float* __restrict__ ev) {
    int j = blockIdx.x * 8 + (threadIdx.x >> 5);
    int lane = threadIdx.x & 31;
    float a[8];
#pragma unroll
    for (int u = 0; u < 8; u++) a[u] = 0.f;
#pragma unroll
    for (int jj = 0; jj < 16; jj++) {
        int c = lane + 32 * jj;
        float w0 = we[(long)j * CV + c];
        float w1 = we[(long)EDV * CV + (long)j * CV + c];
        float4 e0 = *(const float4*)(ev + c * HV);
        float4 e1 = *(const float4*)(ev + CV * HV + c * HV);
        a[0] = fmaf(w0, e0.x, a[0]); a[1] = fmaf(w0, e0.y, a[1]);
        a[2] = fmaf(w0, e0.z, a[2]); a[3] = fmaf(w0, e0.w, a[3]);
        a[4] = fmaf(w1, e1.x, a[4]); a[5] = fmaf(w1, e1.y, a[5]);
        a[6] = fmaf(w1, e1.z, a[6]); a[7] = fmaf(w1, e1.w, a[7]);
    }
#pragma unroll
    for (int u = 0; u < 8; u++) a[u] = warp_red(a[u]);
    if (lane == 0) {
        *(float4*)(g_P + j * 8) = make_float4(a[0], a[1], a[2], a[3]);
        *(float4*)(g_P + j * 8 + 4) = make_float4(a[4], a[5], a[6], a[7]);
    }
}

// ---------------- ae = eattr @ P, both layers ----------------
__global__ void ae_kernel(const float* __restrict__ eattr) {
    int e = blockIdx.x * 8 + (threadIdx.x >> 5);
    int lane = threadIdx.x & 31;
    float a[8];
#pragma unroll
    for (int u = 0; u < 8; u++) a[u] = 0.f;
#pragma unroll
    for (int jj = 0; jj < 24; jj++) {
        int j = lane + 32 * jj;
        float v = eattr[(long)e * EDV + j];
        float4 p0 = *(const float4*)(g_P + j * 8);
        float4 p1 = *(const float4*)(g_P + j * 8 + 4);
        a[0] = fmaf(v, p0.x, a[0]); a[1] = fmaf(v, p0.y, a[1]);
        a[2] = fmaf(v, p0.z, a[2]); a[3] = fmaf(v, p0.w, a[3]);
        a[4] = fmaf(v, p1.x, a[4]); a[5] = fmaf(v, p1.y, a[5]);
        a[6] = fmaf(v, p1.z, a[6]); a[7] = fmaf(v, p1.w, a[7]);
    }
#pragma unroll
    for (int u = 0; u < 8; u++) a[u] = warp_red(a[u]);
    if (lane == 0) {
        *(float4*)(g_ae + (long)e * 8) = make_float4(a[0], a[1], a[2], a[3]);
        *(float4*)(g_ae + (long)e * 8 + 4) = make_float4(a[4], a[5], a[6], a[7]);
    }
}

// ---------------- per-layer reset of softmax state ----------------
__global__ void reset_nodes_kernel() {
    int i = blockIdx.x * blockDim.x + threadIdx.x;
    if (i < NV * HV) { g_maxu[i] = 0u; g_den[i] = 0.f; }
}

// ---------------- attention logits + leaky_relu + segment max ----------------
__global__ void logits_kernel(int l) {
    int e = blockIdx.x * blockDim.x + threadIdx.x;
    if (e >= EV) return;
    int dst = g_dst[e], src = g_src[e], t = g_typ[e];
    float4 ae = *(const float4*)(g_ae + (long)e * (LLV * HV) + l * HV);
    float4 qv = *(const float4*)(g_QK + (long)dst * 64 + t * 4);
    float4 kv = *(const float4*)(g_QK + (long)src * 64 + 32 + t * 4);
    float4 a;
    a.x = qv.x + kv.x + ae.x; a.x = a.x > 0.f ? a.x : 0.2f * a.x;
    a.y = qv.y + kv.y + ae.y; a.y = a.y > 0.f ? a.y : 0.2f * a.y;
    a.z = qv.z + kv.z + ae.z; a.z = a.z > 0.f ? a.z : 0.2f * a.z;
    a.w = qv.w + kv.w + ae.w; a.w = a.w > 0.f ? a.w : 0.2f * a.w;
    *(float4*)(g_alpha + (long)e * HV) = a;
    atomicMax(&g_maxu[dst * HV + 0], fenc(a.x));
    atomicMax(&g_maxu[dst * HV + 1], fenc(a.y));
    atomicMax(&g_maxu[dst * HV + 2], fenc(a.z));
    atomicMax(&g_maxu[dst * HV + 3], fenc(a.w));
}

// ---------------- exp + segment sum ----------------
__global__ void expsum_kernel() {
    int e = blockIdx.x * blockDim.x + threadIdx.x;
    if (e >= EV) return;
    int dst = g_dst[e];
    float4 a = *(const float4*)(g_alpha + (long)e * HV);
    a.x = expf(a.x - fdec(g_maxu[dst * HV + 0]));
    a.y = expf(a.y - fdec(g_maxu[dst * HV + 1]));
    a.z = expf(a.z - fdec(g_maxu[dst * HV + 2]));
    a.w = expf(a.w - fdec(g_maxu[dst * HV + 3]));
    *(float4*)(g_alpha + (long)e * HV) = a;
    atomicAdd(&g_den[dst * HV + 0], a.x);
    atomicAdd(&g_den[dst * HV + 1], a.y);
    atomicAdd(&g_den[dst * HV + 2], a.z);
    atomicAdd(&g_den[dst * HV + 3], a.w);
}

// ---------------- CSR aggregation ----------------
__global__ void agg_kernel(const float* __restrict__ xin, float* __restrict__ xout,
                           const float* __restrict__ bias) {
    int n = blockIdx.x;
    int t = threadIdx.x;
    int h = t >> 5;
    float inv = 1.f / (g_den[n * HV + h] + 1e-16f);
    float4 acc = ((const float4*)bias)[t];
    float4 xr = ((const float4*)(xin + (long)n * CV))[t];
    acc.x += xr.x; acc.y += xr.y; acc.z += xr.z; acc.w += xr.w;
    int b0 = g_off[n], b1 = g_off[n + 1];
    for (int ii = b0; ii < b1; ii++) {
        int e = g_perm[ii];
        float coeff = g_alpha[e * HV + h] * inv;
        const float4* vp = (const float4*)(g_xw + ((long)g_src[e] * RV + g_typ[e]) * CV) + t;
        float4 vv = *vp;
        acc.x = fmaf(coeff, vv.x, acc.x);
        acc.y = fmaf(coeff, vv.y, acc.y);
        acc.z = fmaf(coeff, vv.z, acc.z);
        acc.w = fmaf(coeff, vv.w, acc.w);
    }
    ((float4*)(xout + (long)n * CV))[t] = acc;
}

// ---------------- layernorm ----------------
__global__ void ln_kernel(const float* __restrict__ in, const float* __restrict__ addpre,
                          const float* __restrict__ addpost, float* __restrict__ out,
                          const float* __restrict__ gamma, const float* __restrict__ beta) {
    int n = blockIdx.x, t = threadIdx.x;
    int lane = t & 31, w = t >> 5;
    __shared__ float sred[4];
    float4 x = ((const float4*)(in + (long)n * CV))[t];
    if (addpre) {
        float4 a = ((const float4*)(addpre + (long)n * CV))[t];
        x.x += a.x; x.y += a.y; x.z += a.z; x.w += a.w;
    }
    float s = x.x + x.y + x.z + x.w;
    s = warp_red(s);
    if (!lane) sred[w] = s;
    __syncthreads();
    float mean = (sred[0] + sred[1] + sred[2] + sred[3]) * (1.f / CV);
    __syncthreads();
    float dx = x.x - mean, dy = x.y - mean, dz = x.z - mean, dw = x.w - mean;
    float ss = dx * dx + dy * dy + dz * dz + dw * dw;
    ss = warp_red(ss);
    if (!lane) sred[w] = ss;
    __syncthreads();
    float var = (sred[0] + sred[1] + sred[2] + sred[3]) * (1.f / CV);
    float rstd = rsqrtf(var + 1e-5f);
    float4 g = ((const float4*)gamma)[t];
    float4 b = ((const float4*)beta)[t];
    float4 o;
    o.x = g.x * dx * rstd + b.x;
    o.y = g.y * dy * rstd + b.y;
    o.z = g.z * dz * rstd + b.z;
    o.w = g.w * dw * rstd + b.w;
    if (addpost) {
        float4 p = ((const float4*)(addpost + (long)n * CV))[t];
        o.x += p.x; o.y += p.y; o.z += p.z; o.w += p.w;
    }
    ((float4*)(out + (long)n * CV))[t] = o;
}

// ---------------- launcher ----------------
extern "C" void kernel_launch(void* const* d_in, const int* in_sizes, int n_in,
                              void* d_out, int out_size) {
    const float* x   = (const float*)d_in[0];
    const void*  ei  = d_in[1];
    const void*  et  = d_in[2];
    const float* eattr = (const float*)d_in[3];
    const float* W   = (const float*)d_in[4];
    const float* qm  = (const float*)d_in[5];
    const float* km  = (const float*)d_in[6];
    const float* em  = (const float*)d_in[7];
    const float* we  = (const float*)d_in[8];
    const float* cb  = (const float*)d_in[9];
    const float* lg  = (const float*)d_in[10];
    const float* lb  = (const float*)d_in[11];
    const float* f1w = (const float*)d_in[12];
    const float* f1b = (const float*)d_in[13];
    const float* f2w = (const float*)d_in[14];
    const float* f2b = (const float*)d_in[15];
    float* out = (float*)d_out;

    float *pxw, *pxA, *pxB, *ph0, *ph1, *pxt, *ph0t, *pWt, *pf1t, *pf2t, *pWqk, *pQK;
    cudaGetSymbolAddress((void**)&pxw, g_xw);
    cudaGetSymbolAddress((void**)&pxA, g_xA);
    cudaGetSymbolAddress((void**)&pxB, g_xB);
    cudaGetSymbolAddress((void**)&ph0, g_h0);
    cudaGetSymbolAddress((void**)&ph1, g_h1);
    cudaGetSymbolAddress((void**)&pxt, g_xt);
    cudaGetSymbolAddress((void**)&ph0t, g_h0t);
    cudaGetSymbolAddress((void**)&pWt, g_Wt);
    cudaGetSymbolAddress((void**)&pf1t, g_f1t);
    cudaGetSymbolAddress((void**)&pf2t, g_f2t);
    cudaGetSymbolAddress((void**)&pWqk, g_Wqk);
    cudaGetSymbolAddress((void**)&pQK, g_QK);

    const int TB = 256;
    const int EB = (EV + TB - 1) / TB;
    const int MT = (NV + 127) / 128;

    detect_kernel<<<1, 256>>>((const int*)ei, (const int*)et);
    convert_kernel<<<EB, TB>>>(ei, et);
    reset_cnt_kernel<<<(NV + TB - 1) / TB, TB>>>();
    hist_kernel<<<EB, TB>>>();
    scan_kernel<<<1, 1024>>>();
    scatter_kernel<<<EB, TB>>>();

    // edge-attr projections for BOTH layers in one eattr pass
    p_kernel<<<EDV / 8, 256>>>(we, em);
    ae_kernel<<<EV / 8, 256>>>(eattr);

    // precompute fused QK weights and tf32-rounded weight copies
    wqk_kernel<<<LLV * RV, 256>>>(W, qm, km);
    {
        int n4;
        n4 = LLV * RV * CV * CV / 4;
        cvt_kernel<<<(n4 + TB - 1) / TB, TB>>>(W, pWt, n4);
        n4 = CV * 2 * CV / 4;
        cvt_kernel<<<(n4 + TB - 1) / TB, TB>>>(f1w, pf1t, n4);
        cvt_kernel<<<(n4 + TB - 1) / TB, TB>>>(f2w, pf2t, n4);
    }

    for (int l = 0; l < LLV; l++) {
        const float* xin = (l == 0) ? x : pxB;
        float* xout = (l == 0) ? pxB : pxA;

        // tf32-rounded activation copy
        cvt_kernel<<<(NV * CV / 4 + TB - 1) / TB, TB>>>(xin, pxt, NV * CV / 4);

        // xw[n,r,:] = xt @ Wt[l,r]
        dim3 g1(CV / 128, MT, RV);
        tgemm_k<0><<<g1, 256>>>(pxt, pWt + (long)l * RV * CV * CV, pxw,
                                NV, CV, CV, CV, CV, RV * CV,
                                (long)CV * CV, (long)CV, nullptr, nullptr);

        // QK[n, 0..63] = xt @ Wqk[l]
        dim3 gq(1, MT, 1);
        tgemm_k<0><<<gq, 256>>>(pxt, pWqk + (long)l * CV * 64, pQK,
                                NV, 64, CV, CV, 64, 64, 0, 0, nullptr, nullptr);

        reset_nodes_kernel<<<(NV * HV + TB - 1) / TB, TB>>>();
        logits_kernel<<<EB, TB>>>(l);
        expsum_kernel<<<EB, TB>>>();
        agg_kernel<<<NV, 128>>>(xin, xout, cb + l * CV);
    }

    // h0 = LN(xA + enc_emb)
    ln_kernel<<<NV, 128>>>(pxA, x, nullptr, ph0, lg, lb);
    cvt_kernel<<<(NV * CV / 4 + TB - 1) / TB, TB>>>(ph0, ph0t, NV * CV / 4);
    // h1 = tf32(relu(h0t @ f1t + b1))
    {
        dim3 g2(2 * CV / 128, MT, 1);
        tgemm_k<1><<<g2, 256>>>(ph0t, pf1t, ph1, NV, 2 * CV, CV,
                                CV, 2 * CV, 2 * CV, 0, 0, f1b, nullptr);
    }
    // h2 = h1 @ f2t + b2 + h0  (into pxB)
    {
        dim3 g3(CV / 128, MT, 1);
        tgemm_k<2><<<g3, 256>>>(ph1, pf2t, pxB, NV, CV, 2 * CV,
                                2 * CV, CV, CV, 0, 0, f2b, ph0);
    }
    // out = LN(h2) + enc_emb
    ln_kernel<<<NV, 128>>>(pxB, nullptr, x, out, lg, lb);
}